// round 6
// baseline (speedup 1.0000x reference)
#include <cuda_runtime.h>

#define T_DATA 20000
#define TOFF   256
#define TPAD   20512
#define NXI    20352   // TOFF + 20096 rows (incl. k3 tile over-read pad)

// ---------------- device scratch ----------------
__device__ float2   g_INT2[NXI * 12];    // [x][s] = (IN_e, IN_i), x = TOFF + t
__device__ float2   g_SYN2[12 * TPAD];   // [s][x] = (syn_s, syn_ns)
__device__ float4   g_KER4[12 * 200];    // (kes, kis, ken, kin) per (s,k)
__device__ unsigned g_CTBE[64 * 12];     // permuted bit layout (matches k1f ballots)
__device__ unsigned g_CTBI[16 * 12];

__device__ __forceinline__ float sigmoidf_(float x) {
    return 1.0f / (1.0f + __expf(-x));
}

// packed f32x2 helpers (Blackwell)
#define FMA2(acc, a, b) \
    asm("fma.rn.f32x2 %0, %1, %2, %3;" : "=l"(acc) : "l"(a), "l"(b), "l"(acc))
#define PACK2(out, lo, hi) \
    asm("mov.b64 %0, {%1, %2};" : "=l"(out) : "f"(lo), "f"(hi))
#define UNPACK2(lo, hi, in) \
    asm("mov.b64 {%0, %1}, %2;" : "=f"(lo), "=f"(hi) : "l"(in))

// ---------------- K0a: pack C_syn into permuted bitmasks ----------------
__global__ void k0a(const float* __restrict__ Ce, const float* __restrict__ Ci) {
    int gid = blockIdx.x * 256 + threadIdx.x;
    if (gid < 768) {
        int wc = gid / 12, s = gid % 12;
        unsigned m = 0;
        #pragma unroll 4
        for (int l = 0; l < 32; ++l) {
            int idx = 128 * (wc >> 2) + 4 * l + (wc & 3);
            if (idx < 2000 && Ce[s * 2000 + idx] != 0.f) m |= (1u << l);
        }
        g_CTBE[wc * 12 + s] = m;
    } else if (gid < 960) {
        int j = gid - 768;
        int wc = j / 12, s = j % 12;
        unsigned m = 0;
        #pragma unroll 4
        for (int l = 0; l < 32; ++l) {
            int idx = 128 * (wc >> 2) + 4 * l + (wc & 3);
            if (idx < 500 && Ci[s * 500 + idx] != 0.f) m |= (1u << l);
        }
        g_CTBI[wc * 12 + s] = m;
    }
}

__device__ __forceinline__ float coef1(const float* __restrict__ W,
                                       const float* __restrict__ D,
                                       int s, int c, float t) {
    float ts = fmaxf(t - expf(D[s * 2 + c]), 0.f);
    float acc = 0.f;
    #pragma unroll
    for (int b = 0; b < 3; ++b) {
        float tau = expf(0.5f * (float)b);
        float tt  = ts / tau;
        acc += W[s * 6 + b * 2 + c] * tt * expf(-tt);
    }
    return acc;
}

// ---------------- K1f: fused bit-pack + popcount GEMM (+prep side-blocks) ----
__global__ void __launch_bounds__(256) k1f(const float4* __restrict__ Se4,
                                           const float4* __restrict__ Si4,
                                           const float* __restrict__ Wss,
                                           const float* __restrict__ Wns,
                                           const float* __restrict__ Dss,
                                           const float* __restrict__ Dns) {
    if (blockIdx.x >= 2500) {
        int gid = (blockIdx.x - 2500) * 256 + threadIdx.x;
        if (gid < 2400) {
            int s = gid / 200, k = gid % 200;
            float t = (float)k;
            float4 o;
            o.x = coef1(Wss, Dss, s, 0, t);
            o.y = coef1(Wss, Dss, s, 1, t);
            o.z = coef1(Wns, Dns, s, 0, t);
            o.w = coef1(Wns, Dns, s, 1, t);
            g_KER4[gid] = o;
        } else if (gid < 5472) {
            g_INT2[gid - 2400] = make_float2(0.f, 0.f);       // x < 256, all s
        } else if (gid < 8544) {
            int j = gid - 5472;
            int s = j >> 8, x = j & 255;
            g_SYN2[s * TPAD + x] = make_float2(0.f, 0.f);
        }
        return;
    }
    __shared__ unsigned sCE[768], sCI[192];
    int tid = threadIdx.x;
    for (int i = tid; i < 768; i += 256) sCE[i] = g_CTBE[i];
    if (tid < 192) sCI[tid] = g_CTBI[tid];
    __syncthreads();

    int lane = tid & 31;
    int row  = blockIdx.x * 8 + (tid >> 5);
    const float4* rE = Se4 + (size_t)row * 500;
    const float4* rI = Si4 + (size_t)row * 125;
    int lc = (lane < 12) ? lane : 0;
    int accE = 0, accI = 0;

    #pragma unroll
    for (int w = 0; w < 16; ++w) {
        int f = w * 32 + lane;
        float4 v = (f < 500) ? __ldg(rE + f) : make_float4(0.f, 0.f, 0.f, 0.f);
        unsigned m0 = __ballot_sync(0xffffffffu, v.x != 0.f);
        unsigned m1 = __ballot_sync(0xffffffffu, v.y != 0.f);
        unsigned m2 = __ballot_sync(0xffffffffu, v.z != 0.f);
        unsigned m3 = __ballot_sync(0xffffffffu, v.w != 0.f);
        int b = w * 48 + lc;
        accE += __popc(m0 & sCE[b]);
        accE += __popc(m1 & sCE[b + 12]);
        accE += __popc(m2 & sCE[b + 24]);
        accE += __popc(m3 & sCE[b + 36]);
    }
    #pragma unroll
    for (int w = 0; w < 4; ++w) {
        int f = w * 32 + lane;
        float4 v = (f < 125) ? __ldg(rI + f) : make_float4(0.f, 0.f, 0.f, 0.f);
        unsigned m0 = __ballot_sync(0xffffffffu, v.x != 0.f);
        unsigned m1 = __ballot_sync(0xffffffffu, v.y != 0.f);
        unsigned m2 = __ballot_sync(0xffffffffu, v.z != 0.f);
        unsigned m3 = __ballot_sync(0xffffffffu, v.w != 0.f);
        int b = w * 48 + lc;
        accI += __popc(m0 & sCI[b]);
        accI += __popc(m1 & sCI[b + 12]);
        accI += __popc(m2 & sCI[b + 24]);
        accI += __popc(m3 & sCI[b + 36]);
    }
    if (lane < 12)
        g_INT2[(TOFF + row) * 12 + lane] = make_float2((float)accE, (float)accI);
}

// ---------------- K3 v2: 200-tap conv, sliding register window + f32x2 ------
// 157 blocks x 128 t. 12 warps, warp = subunit. Each lane owns 4 adjacent
// outputs t = t0 + 4*lane + j. Data staged in 4 mod-4 "planes" so the per-k
// incoming load is stride-1 (conflict-free); one LDS.64 feeds 16 FMAs,
// executed as 8 fma.rn.f32x2 on (e,i)-packed operands.
__global__ void __launch_bounds__(384) k3_conv() {
    __shared__ unsigned long long sP[12][4][82];   // [s][xx&3][xx>>2], xx = X-(t0-200)
    int tid = threadIdx.x;
    int t0  = blockIdx.x * 128;
    int rowbase = (TOFF + t0 - 200) * 12;
    for (int i = tid; i < 3936; i += 384) {        // 328 xx * 12 s
        int xx = i / 12, s = i % 12;
        sP[s][xx & 3][xx >> 2] =
            *(const unsigned long long*)&g_INT2[rowbase + xx * 12 + s];
    }
    __syncthreads();

    int warp = tid >> 5, lane = tid & 31;
    int s = warp;
    unsigned long long as0 = 0, as1 = 0, as2 = 0, as3 = 0;
    unsigned long long an0 = 0, an1 = 0, an2 = 0, an3 = 0;
    unsigned long long W0 = sP[s][0][50 + lane];
    unsigned long long W1 = sP[s][1][50 + lane];
    unsigned long long W2 = sP[s][2][50 + lane];
    unsigned long long W3 = sP[s][3][50 + lane];
    const float4* kp = g_KER4 + s * 200;

    for (int K = 0; K < 50; ++K) {
        int q = 49 - K + lane;
        float4 kc; unsigned long long cs, cn;
        // u=0 (k=4K): acc[j] uses W[j]; incoming -> plane 3
        kc = __ldg(kp + 4 * K + 0); PACK2(cs, kc.x, kc.y); PACK2(cn, kc.z, kc.w);
        FMA2(as0, W0, cs); FMA2(an0, W0, cn);
        FMA2(as1, W1, cs); FMA2(an1, W1, cn);
        FMA2(as2, W2, cs); FMA2(an2, W2, cn);
        FMA2(as3, W3, cs); FMA2(an3, W3, cn);
        W3 = sP[s][3][q];
        // u=1: planes [3,0,1,2]; incoming -> plane 2
        kc = __ldg(kp + 4 * K + 1); PACK2(cs, kc.x, kc.y); PACK2(cn, kc.z, kc.w);
        FMA2(as0, W3, cs); FMA2(an0, W3, cn);
        FMA2(as1, W0, cs); FMA2(an1, W0, cn);
        FMA2(as2, W1, cs); FMA2(an2, W1, cn);
        FMA2(as3, W2, cs); FMA2(an3, W2, cn);
        W2 = sP[s][2][q];
        // u=2: planes [2,3,0,1]; incoming -> plane 1
        kc = __ldg(kp + 4 * K + 2); PACK2(cs, kc.x, kc.y); PACK2(cn, kc.z, kc.w);
        FMA2(as0, W2, cs); FMA2(an0, W2, cn);
        FMA2(as1, W3, cs); FMA2(an1, W3, cn);
        FMA2(as2, W0, cs); FMA2(an2, W0, cn);
        FMA2(as3, W1, cs); FMA2(an3, W1, cn);
        W1 = sP[s][1][q];
        // u=3: planes [1,2,3,0]; incoming -> plane 0
        kc = __ldg(kp + 4 * K + 3); PACK2(cs, kc.x, kc.y); PACK2(cn, kc.z, kc.w);
        FMA2(as0, W1, cs); FMA2(an0, W1, cn);
        FMA2(as1, W2, cs); FMA2(an1, W2, cn);
        FMA2(as2, W3, cs); FMA2(an2, W3, cn);
        FMA2(as3, W0, cs); FMA2(an3, W0, cn);
        W0 = sP[s][0][q];
    }

    int t = t0 + 4 * lane;
    if (t < T_DATA) {
        float lo, hi, vs0, vs1, vs2, vs3, vn0, vn1, vn2, vn3;
        UNPACK2(lo, hi, as0); vs0 = lo + hi;
        UNPACK2(lo, hi, as1); vs1 = lo + hi;
        UNPACK2(lo, hi, as2); vs2 = lo + hi;
        UNPACK2(lo, hi, as3); vs3 = lo + hi;
        UNPACK2(lo, hi, an0); vn0 = lo + hi;
        UNPACK2(lo, hi, an1); vn1 = lo + hi;
        UNPACK2(lo, hi, an2); vn2 = lo + hi;
        UNPACK2(lo, hi, an3); vn3 = lo + hi;
        float4* dst = (float4*)&g_SYN2[s * TPAD + TOFF + t];
        dst[0] = make_float4(vs0, vn0, vs1, vn1);
        dst[1] = make_float4(vs2, vn2, vs3, vn3);
    }
}

// ---------------- K4 v2: barrier-free redundant-cone cascade ----------------
// One thread per t recomputes its 13-column dependency cone in registers
// (level i needed at columns t-d, d <= 12-i). 90 sigmoids/thread, zero
// inter-level barriers; syn data staged once into smem.
__global__ void __launch_bounds__(128) k4_scan(const float* __restrict__ Cden,
                                               const float* __restrict__ Ths,
                                               const float* __restrict__ Thns,
                                               const float* __restrict__ Wssub,
                                               const float* __restrict__ Wnssub,
                                               float* __restrict__ out) {
    __shared__ float sS[12][140], sNS[12][140];   // m <-> t = t0 - 12 + m
    __shared__ float sout[128 * 35];
    __shared__ float cwns[144], cds[144];
    __shared__ float ths[12], thns[12], ws[12], wns[12];
    int tid = threadIdx.x;
    int t0  = blockIdx.x * 128;
    for (int v = tid; v < 144; v += 128) {
        float c = Cden[v];
        cds [v] = c;
        cwns[v] = c * Wnssub[v % 12];
    }
    if (tid < 12) {
        ths [tid] = Ths[tid];
        thns[tid] = Thns[tid];
        ws  [tid] = Wssub[tid];
        wns [tid] = Wnssub[tid];
    }
    for (int i = tid; i < 1680; i += 128) {        // 12 s * 140 m
        int s = i / 140, m = i % 140;
        float2 v = g_SYN2[s * TPAD + TOFF + t0 - 12 + m];
        sS [s][m] = v.x;
        sNS[s][m] = v.y;
    }
    __syncthreads();

    int t = t0 + tid;
    float prev[12], cur[12], xm1[12];
    #pragma unroll
    for (int d = 12; d >= 0; --d) {
        int tc = t - d;
        int m  = tid + 12 - d;
        #pragma unroll
        for (int i = 0; i < 12; ++i) {
            if (i > 12 - d) break;                 // compile-time per unrolled d
            float x = sNS[i][m] + thns[i];
            #pragma unroll
            for (int j = 0; j < i; ++j) x = fmaf(cwns[i * 12 + j], prev[j], x);
            cur[i] = (tc >= 0) ? sigmoidf_(x) : 0.f;
        }
        #pragma unroll
        for (int i = 0; i < 12; ++i) {
            if (i > 12 - d) break;
            prev[i] = cur[i];
        }
        if (d == 1) {
            #pragma unroll
            for (int j = 0; j < 12; ++j) xm1[j] = cur[j];
        }
    }

    if (t < T_DATA) {
        float ysp[12];
        if (t == 0) {
            #pragma unroll
            for (int j = 0; j < 12; ++j) ysp[j] = 0.f;
        } else {
            float x0 = sS[0][tid + 11] + ths[0];   // syn_s[0] at t-1
            ysp[0] = sigmoidf_(x0) * ws[0];
            #pragma unroll
            for (int j = 1; j < 12; ++j) ysp[j] = xm1[j] * ws[j];
        }
        float* o = sout + tid * 35;
        #pragma unroll
        for (int i = 0; i < 12; ++i) {
            float xs = sS[i][tid + 12] + ths[i];
            #pragma unroll
            for (int j = 0; j < i; ++j) xs = fmaf(cds[i * 12 + j], ysp[j], xs);
            float sg = sigmoidf_(xs);
            o[i]      = (i == 0) ? sg * ws[0] : cur[i] * ws[i];
            o[12 + i] = cur[i] * wns[i];
            if (i >= 1) o[24 + i - 1] = sg;
        }
    }
    __syncthreads();
    int nvalid = T_DATA - t0; if (nvalid > 128) nvalid = 128;
    float* ob = out + (size_t)t0 * 35;
    if (nvalid == 128) {
        float4* o4 = (float4*)ob;
        const float4* s4 = (const float4*)sout;
        for (int i = tid; i < 1120; i += 128) o4[i] = s4[i];
    } else {
        int nf = nvalid * 35;
        for (int i = tid; i < nf; i += 128) ob[i] = sout[i];
    }
}

// ---------------- launch ----------------
extern "C" void kernel_launch(void* const* d_in, const int* in_sizes, int n_in,
                              void* d_out, int out_size) {
    const float* S_e      = (const float*)d_in[0];
    const float* S_i      = (const float*)d_in[1];
    const float* C_syn_e  = (const float*)d_in[2];
    const float* C_syn_i  = (const float*)d_in[3];
    const float* C_den    = (const float*)d_in[4];
    const float* W_s_syn  = (const float*)d_in[5];
    const float* W_ns_syn = (const float*)d_in[6];
    const float* D_s      = (const float*)d_in[7];
    const float* D_ns     = (const float*)d_in[8];
    const float* Theta_s  = (const float*)d_in[9];
    const float* Theta_ns = (const float*)d_in[10];
    const float* W_s_sub  = (const float*)d_in[11];
    const float* W_ns_sub = (const float*)d_in[12];
    float* out = (float*)d_out;

    k0a<<<4, 256>>>(C_syn_e, C_syn_i);
    k1f<<<2534, 256>>>((const float4*)S_e, (const float4*)S_i,
                       W_s_syn, W_ns_syn, D_s, D_ns);
    k3_conv<<<157, 384>>>();
    k4_scan<<<157, 128>>>(C_den, Theta_s, Theta_ns, W_s_sub, W_ns_sub, out);
}

// round 7
// speedup vs baseline: 1.3494x; 1.3494x over previous
#include <cuda_runtime.h>

#define T_DATA 20000
#define TOFF   256
#define NXI    20352   // rows in g_INT2 (TOFF + 20000 + pad for tile over-read)

// ---------------- device scratch ----------------
__device__ float2   g_INT2[NXI * 12];    // [x][s] = (IN_e, IN_i), x = TOFF + t
__device__ float4   g_KER4[12 * 200];    // (kes, kis, ken, kin) per (s,k)
__device__ unsigned g_CTBE[64 * 12];     // permuted bit layout (matches k1f ballots)
__device__ unsigned g_CTBI[16 * 12];

__device__ __forceinline__ float sigmoidf_(float x) {
    return 1.0f / (1.0f + __expf(-x));
}

// ---------------- K0a: pack C_syn via coalesced float4 + ballots ----------------
// mask word (4w+c, s): bit l = (C[s][128w + 4l + c] != 0)  == ballot of
// component c of float4 chunk w across lanes. One warp per (w, s).
__global__ void __launch_bounds__(960) k0a(const float4* __restrict__ Ce4,
                                           const float4* __restrict__ Ci4) {
    int warp = threadIdx.x >> 5, lane = threadIdx.x & 31;
    int gw = blockIdx.x * 30 + warp;                 // 0..239
    if (gw < 192) {                                   // E: 16 chunks x 12 subunits
        int w = gw / 12, s = gw % 12;
        int f = w * 32 + lane;
        float4 v = (f < 500) ? __ldg(Ce4 + s * 500 + f)
                             : make_float4(0.f, 0.f, 0.f, 0.f);
        unsigned m0 = __ballot_sync(0xffffffffu, v.x != 0.f);
        unsigned m1 = __ballot_sync(0xffffffffu, v.y != 0.f);
        unsigned m2 = __ballot_sync(0xffffffffu, v.z != 0.f);
        unsigned m3 = __ballot_sync(0xffffffffu, v.w != 0.f);
        if (lane == 0) {
            g_CTBE[(4 * w + 0) * 12 + s] = m0;
            g_CTBE[(4 * w + 1) * 12 + s] = m1;
            g_CTBE[(4 * w + 2) * 12 + s] = m2;
            g_CTBE[(4 * w + 3) * 12 + s] = m3;
        }
    } else if (gw < 240) {                            // I: 4 chunks x 12 subunits
        int j = gw - 192;
        int w = j / 12, s = j % 12;
        int f = w * 32 + lane;
        float4 v = (f < 125) ? __ldg(Ci4 + s * 125 + f)
                             : make_float4(0.f, 0.f, 0.f, 0.f);
        unsigned m0 = __ballot_sync(0xffffffffu, v.x != 0.f);
        unsigned m1 = __ballot_sync(0xffffffffu, v.y != 0.f);
        unsigned m2 = __ballot_sync(0xffffffffu, v.z != 0.f);
        unsigned m3 = __ballot_sync(0xffffffffu, v.w != 0.f);
        if (lane == 0) {
            g_CTBI[(4 * w + 0) * 12 + s] = m0;
            g_CTBI[(4 * w + 1) * 12 + s] = m1;
            g_CTBI[(4 * w + 2) * 12 + s] = m2;
            g_CTBI[(4 * w + 3) * 12 + s] = m3;
        }
    }
}

__device__ __forceinline__ float coef1(const float* __restrict__ W,
                                       const float* __restrict__ D,
                                       int s, int c, float t) {
    float ts = fmaxf(t - expf(D[s * 2 + c]), 0.f);
    float acc = 0.f;
    #pragma unroll
    for (int b = 0; b < 3; ++b) {
        float tau = expf(0.5f * (float)b);
        float tt  = ts / tau;
        acc += W[s * 6 + b * 2 + c] * tt * expf(-tt);
    }
    return acc;
}

// ---------------- K1f: fused bit-pack + popcount GEMM, pipelined loads --------
__global__ void __launch_bounds__(256) k1f(const float4* __restrict__ Se4,
                                           const float4* __restrict__ Si4,
                                           const float* __restrict__ Wss,
                                           const float* __restrict__ Wns,
                                           const float* __restrict__ Dss,
                                           const float* __restrict__ Dns) {
    if (blockIdx.x >= 2500) {
        int gid = (blockIdx.x - 2500) * 256 + threadIdx.x;
        if (gid < 2400) {
            int s = gid / 200, k = gid % 200;
            float t = (float)k;
            float4 o;
            o.x = coef1(Wss, Dss, s, 0, t);
            o.y = coef1(Wss, Dss, s, 1, t);
            o.z = coef1(Wns, Dns, s, 0, t);
            o.w = coef1(Wns, Dns, s, 1, t);
            g_KER4[gid] = o;
        } else if (gid < 5472) {
            g_INT2[gid - 2400] = make_float2(0.f, 0.f);   // zero pad x < 256
        }
        return;
    }
    __shared__ unsigned sCE[768], sCI[192];
    int tid = threadIdx.x;
    for (int i = tid; i < 768; i += 256) sCE[i] = g_CTBE[i];
    if (tid < 192) sCI[tid] = g_CTBI[tid];
    __syncthreads();

    int lane = tid & 31;
    int row  = blockIdx.x * 8 + (tid >> 5);
    const float4* rE = Se4 + (size_t)row * 500;
    const float4* rI = Si4 + (size_t)row * 125;
    int lc = (lane < 12) ? lane : 0;
    int accE = 0, accI = 0;
    const float4 z4 = make_float4(0.f, 0.f, 0.f, 0.f);

    // 4-deep prefetch ring: next load issued before this iteration's ballots,
    // keeping ~4 loads in flight across the ballot convergence points.
    float4 vb[4];
    #pragma unroll
    for (int j = 0; j < 4; ++j) vb[j] = __ldg(rE + j * 32 + lane);

    #pragma unroll
    for (int w = 0; w < 16; ++w) {
        float4 v = vb[w & 3];
        int wn = w + 4;
        if (wn < 16) {
            int f = wn * 32 + lane;
            vb[w & 3] = (f < 500) ? __ldg(rE + f) : z4;
        } else {
            int f = (wn - 16) * 32 + lane;
            vb[w & 3] = (f < 125) ? __ldg(rI + f) : z4;
        }
        unsigned m0 = __ballot_sync(0xffffffffu, v.x != 0.f);
        unsigned m1 = __ballot_sync(0xffffffffu, v.y != 0.f);
        unsigned m2 = __ballot_sync(0xffffffffu, v.z != 0.f);
        unsigned m3 = __ballot_sync(0xffffffffu, v.w != 0.f);
        int b = w * 48 + lc;
        accE += __popc(m0 & sCE[b]);
        accE += __popc(m1 & sCE[b + 12]);
        accE += __popc(m2 & sCE[b + 24]);
        accE += __popc(m3 & sCE[b + 36]);
    }
    #pragma unroll
    for (int w = 0; w < 4; ++w) {
        float4 v = vb[w];
        unsigned m0 = __ballot_sync(0xffffffffu, v.x != 0.f);
        unsigned m1 = __ballot_sync(0xffffffffu, v.y != 0.f);
        unsigned m2 = __ballot_sync(0xffffffffu, v.z != 0.f);
        unsigned m3 = __ballot_sync(0xffffffffu, v.w != 0.f);
        int b = w * 48 + lc;
        accI += __popc(m0 & sCI[b]);
        accI += __popc(m1 & sCI[b + 12]);
        accI += __popc(m2 & sCI[b + 24]);
        accI += __popc(m3 & sCI[b + 36]);
    }
    if (lane < 12)
        g_INT2[(TOFF + row) * 12 + lane] = make_float2((float)accE, (float)accI);
}

// ---------------- K34: fused conv + cascade + output ----------------
// 125 blocks x 160 t, 768 threads. Conv (warp = (half, s), 100 taps each,
// r=6 covers the 12-step halo) feeds the 12-level lower-triangular cascade
// entirely in smem; g_SYN2 round-trip eliminated. Smem regions phase-aliased.
#define SP_OFF   0        // float2[12][192] conv partials (half=1)
#define SNS_OFF  4608     // float [12*192] syn_ns
#define SS_OFF   6912     // float [12*192] syn_s
#define XNO_OFF  9216     // float [12*176] cascade levels
#define BUFSZ    11328    // floats; sIN (9408) and sout (5600) alias offset 0

__global__ void __launch_bounds__(768) k34(const float* __restrict__ Cden,
                                           const float* __restrict__ Ths,
                                           const float* __restrict__ Thns,
                                           const float* __restrict__ Wssub,
                                           const float* __restrict__ Wnssub,
                                           float* __restrict__ out) {
    __shared__ __align__(16) float buf[BUFSZ];
    __shared__ float cwns[144], cds[144];
    __shared__ float ths[12], thns[12], ws[12], wns[12];
    int tid = threadIdx.x;
    int t0  = blockIdx.x * 160;

    if (tid < 144) {
        float c = Cden[tid];
        cds [tid] = c;
        cwns[tid] = c * Wnssub[tid % 12];
    }
    if (tid >= 160 && tid < 172) {
        int q = tid - 160;
        ths [q] = Ths[q];
        thns[q] = Thns[q];
        ws  [q] = Wssub[q];
        wns [q] = Wnssub[q];
    }

    // ---- stage IN window: x = TOFF + t0 - 211 + xx, xx in [0, 392) ----
    float2* sIN = (float2*)buf;                      // [s][xx], pitch 392
    int rowbase = (TOFF + t0 - 211) * 12;
    for (int i = tid; i < 4704; i += 768) {          // 392 * 12
        int xx = i / 12, s = i % 12;
        sIN[s * 392 + xx] = g_INT2[rowbase + i];
    }
    __syncthreads();

    // ---- conv: outputs o = lane + 32r - 12 (rel t0), r = 0..5 ----
    int warp = tid >> 5, lane = tid & 31;
    int s = warp % 12, half = warp / 12;
    float as[6], an[6];
    #pragma unroll
    for (int r = 0; r < 6; ++r) { as[r] = 0.f; an[r] = 0.f; }
    const float4*  kp = g_KER4 + s * 200 + half * 100;
    const float2*  dp = sIN + s * 392 + (199 - half * 100) + lane;
    #pragma unroll 2
    for (int kk = 0; kk < 100; ++kk) {
        float4 kc = __ldg(kp + kk);
        #pragma unroll
        for (int r = 0; r < 6; ++r) {
            float2 ei = dp[32 * r - kk];
            as[r] = fmaf(kc.x, ei.x, fmaf(kc.y, ei.y, as[r]));
            an[r] = fmaf(kc.z, ei.x, fmaf(kc.w, ei.y, an[r]));
        }
    }
    __syncthreads();                                  // sIN dead

    // ---- combine halves into sS / sNS (col m = o + 12 = lane + 32r) ----
    float2* sP = (float2*)buf;                        // [s][m], pitch 192
    if (half == 1) {
        #pragma unroll
        for (int r = 0; r < 6; ++r)
            sP[s * 192 + lane + 32 * r] = make_float2(as[r], an[r]);
    }
    __syncthreads();
    if (half == 0) {
        #pragma unroll
        for (int r = 0; r < 6; ++r) {
            int m = lane + 32 * r;
            float2 p = sP[s * 192 + m];
            buf[SS_OFF  + s * 192 + m] = as[r] + p.x;
            buf[SNS_OFF + s * 192 + m] = an[r] + p.y;
        }
    }
    __syncthreads();                                  // sP dead after next use note

    // ---- cascade: 12 levels over cols m = 0..171 (t = t0 - 12 + m) ----
    #pragma unroll
    for (int i = 0; i < 12; ++i) {
        if (tid < 172) {
            int t = t0 - 12 + tid;
            float v = 0.f;
            if (t >= 0) {
                float x = buf[SNS_OFF + i * 192 + tid] + thns[i];
                #pragma unroll
                for (int j = 0; j < i; ++j) {
                    float yp = (tid > 0) ? buf[XNO_OFF + j * 176 + tid - 1] : 0.f;
                    x = fmaf(cwns[i * 12 + j], yp, x);
                }
                v = sigmoidf_(x);
            }
            buf[XNO_OFF + i * 176 + tid] = v;
        }
        __syncthreads();
    }

    // ---- epilogue: per-t outputs into sout (aliases sP region, dead) ----
    if (tid < 160) {
        int t = t0 + tid, h = tid + 12;
        float ysp[12];
        if (t == 0) {
            #pragma unroll
            for (int j = 0; j < 12; ++j) ysp[j] = 0.f;
        } else {
            float x0 = buf[SS_OFF + 0 * 192 + tid + 11] + ths[0];
            ysp[0] = sigmoidf_(x0) * ws[0];
            #pragma unroll
            for (int j = 1; j < 12; ++j)
                ysp[j] = buf[XNO_OFF + j * 176 + h - 1] * ws[j];
        }
        float* o = buf + tid * 35;                    // sout: 0..5600
        #pragma unroll
        for (int i = 0; i < 12; ++i) {
            float xs = buf[SS_OFF + i * 192 + tid + 12] + ths[i];
            #pragma unroll
            for (int j = 0; j < i; ++j) xs = fmaf(cds[i * 12 + j], ysp[j], xs);
            float sg  = sigmoidf_(xs);
            float xti = buf[XNO_OFF + i * 176 + h];
            o[i]      = (i == 0) ? sg * ws[0] : xti * ws[i];
            o[12 + i] = xti * wns[i];
            if (i >= 1) o[24 + i - 1] = sg;
        }
    }
    __syncthreads();
    float4* ob = (float4*)(out + (size_t)t0 * 35);    // 5600 floats = 1400 f4
    const float4* sb = (const float4*)buf;
    for (int i = tid; i < 1400; i += 768) ob[i] = sb[i];
}

// ---------------- launch ----------------
extern "C" void kernel_launch(void* const* d_in, const int* in_sizes, int n_in,
                              void* d_out, int out_size) {
    const float* S_e      = (const float*)d_in[0];
    const float* S_i      = (const float*)d_in[1];
    const float* C_syn_e  = (const float*)d_in[2];
    const float* C_syn_i  = (const float*)d_in[3];
    const float* C_den    = (const float*)d_in[4];
    const float* W_s_syn  = (const float*)d_in[5];
    const float* W_ns_syn = (const float*)d_in[6];
    const float* D_s      = (const float*)d_in[7];
    const float* D_ns     = (const float*)d_in[8];
    const float* Theta_s  = (const float*)d_in[9];
    const float* Theta_ns = (const float*)d_in[10];
    const float* W_s_sub  = (const float*)d_in[11];
    const float* W_ns_sub = (const float*)d_in[12];
    float* out = (float*)d_out;

    k0a<<<8, 960>>>((const float4*)C_syn_e, (const float4*)C_syn_i);
    k1f<<<2522, 256>>>((const float4*)S_e, (const float4*)S_i,
                       W_s_syn, W_ns_syn, D_s, D_ns);
    k34<<<125, 768>>>(C_den, Theta_s, Theta_ns, W_s_sub, W_ns_sub, out);
}

// round 9
// speedup vs baseline: 1.4595x; 1.0816x over previous
#include <cuda_runtime.h>

#define T_DATA 20000
#define TOFF   256
#define NXI    20400   // rows in g_INT2 (TOFF + 20000 + pad for k34 tile over-read)
#define TILE   136     // k34 outputs per block; 148*136 >= 20000

// ---------------- device scratch ----------------
__device__ float2   g_INT2[NXI * 12];    // [x][s] = (IN_e, IN_i), x = TOFF + t
__device__ float4   g_KER4[12 * 200];    // (kes, kis, ken, kin) per (s,k)
__device__ unsigned g_CTBE[64 * 12];     // permuted bit layout (matches k1f ballots)
__device__ unsigned g_CTBI[16 * 12];

__device__ __forceinline__ float sigmoidf_(float x) {
    return 1.0f / (1.0f + __expf(-x));
}

// packed f32x2 helpers (Blackwell)
#define FMA2(acc, a, b) \
    asm("fma.rn.f32x2 %0, %1, %2, %3;" : "=l"(acc) : "l"(a), "l"(b), "l"(acc))
#define PACK2(out, lo, hi) \
    asm("mov.b64 %0, {%1, %2};" : "=l"(out) : "f"(lo), "f"(hi))
#define UNPACK2(lo, hi, in) \
    asm("mov.b64 {%0, %1}, %2;" : "=f"(lo), "=f"(hi) : "l"(in))

// ---------------- K0a: pack C_syn via coalesced float4 + ballots ----------------
__global__ void __launch_bounds__(960) k0a(const float4* __restrict__ Ce4,
                                           const float4* __restrict__ Ci4) {
    int warp = threadIdx.x >> 5, lane = threadIdx.x & 31;
    int gw = blockIdx.x * 30 + warp;                 // 0..239
    if (gw < 192) {                                   // E: 16 chunks x 12 subunits
        int w = gw / 12, s = gw % 12;
        int f = w * 32 + lane;
        float4 v = (f < 500) ? __ldg(Ce4 + s * 500 + f)
                             : make_float4(0.f, 0.f, 0.f, 0.f);
        unsigned m0 = __ballot_sync(0xffffffffu, v.x != 0.f);
        unsigned m1 = __ballot_sync(0xffffffffu, v.y != 0.f);
        unsigned m2 = __ballot_sync(0xffffffffu, v.z != 0.f);
        unsigned m3 = __ballot_sync(0xffffffffu, v.w != 0.f);
        if (lane == 0) {
            g_CTBE[(4 * w + 0) * 12 + s] = m0;
            g_CTBE[(4 * w + 1) * 12 + s] = m1;
            g_CTBE[(4 * w + 2) * 12 + s] = m2;
            g_CTBE[(4 * w + 3) * 12 + s] = m3;
        }
    } else if (gw < 240) {                            // I: 4 chunks x 12 subunits
        int j = gw - 192;
        int w = j / 12, s = j % 12;
        int f = w * 32 + lane;
        float4 v = (f < 125) ? __ldg(Ci4 + s * 125 + f)
                             : make_float4(0.f, 0.f, 0.f, 0.f);
        unsigned m0 = __ballot_sync(0xffffffffu, v.x != 0.f);
        unsigned m1 = __ballot_sync(0xffffffffu, v.y != 0.f);
        unsigned m2 = __ballot_sync(0xffffffffu, v.z != 0.f);
        unsigned m3 = __ballot_sync(0xffffffffu, v.w != 0.f);
        if (lane == 0) {
            g_CTBI[(4 * w + 0) * 12 + s] = m0;
            g_CTBI[(4 * w + 1) * 12 + s] = m1;
            g_CTBI[(4 * w + 2) * 12 + s] = m2;
            g_CTBI[(4 * w + 3) * 12 + s] = m3;
        }
    }
}

__device__ __forceinline__ float coef1(const float* __restrict__ W,
                                       const float* __restrict__ D,
                                       int s, int c, float t) {
    float ts = fmaxf(t - expf(D[s * 2 + c]), 0.f);
    float acc = 0.f;
    #pragma unroll
    for (int b = 0; b < 3; ++b) {
        float tau = expf(0.5f * (float)b);
        float tt  = ts / tau;
        acc += W[s * 6 + b * 2 + c] * tt * expf(-tt);
    }
    return acc;
}

// ---------------- K1f: fused bit-pack + popcount GEMM, pipelined loads --------
__global__ void __launch_bounds__(256) k1f(const float4* __restrict__ Se4,
                                           const float4* __restrict__ Si4,
                                           const float* __restrict__ Wss,
                                           const float* __restrict__ Wns,
                                           const float* __restrict__ Dss,
                                           const float* __restrict__ Dns) {
    if (blockIdx.x >= 2500) {
        int gid = (blockIdx.x - 2500) * 256 + threadIdx.x;
        if (gid < 2400) {
            int s = gid / 200, k = gid % 200;
            float t = (float)k;
            float4 o;
            o.x = coef1(Wss, Dss, s, 0, t);
            o.y = coef1(Wss, Dss, s, 1, t);
            o.z = coef1(Wns, Dns, s, 0, t);
            o.w = coef1(Wns, Dns, s, 1, t);
            g_KER4[gid] = o;
        } else if (gid < 5472) {
            g_INT2[gid - 2400] = make_float2(0.f, 0.f);   // zero pad x < 256
        }
        return;
    }
    __shared__ unsigned sCE[768], sCI[192];
    int tid = threadIdx.x;
    for (int i = tid; i < 768; i += 256) sCE[i] = g_CTBE[i];
    if (tid < 192) sCI[tid] = g_CTBI[tid];
    __syncthreads();

    int lane = tid & 31;
    int row  = blockIdx.x * 8 + (tid >> 5);
    const float4* rE = Se4 + (size_t)row * 500;
    const float4* rI = Si4 + (size_t)row * 125;
    int lc = (lane < 12) ? lane : 0;
    int accE = 0, accI = 0;
    const float4 z4 = make_float4(0.f, 0.f, 0.f, 0.f);

    float4 vb[4];
    #pragma unroll
    for (int j = 0; j < 4; ++j) vb[j] = __ldg(rE + j * 32 + lane);

    #pragma unroll
    for (int w = 0; w < 16; ++w) {
        float4 v = vb[w & 3];
        int wn = w + 4;
        if (wn < 16) {
            int f = wn * 32 + lane;
            vb[w & 3] = (f < 500) ? __ldg(rE + f) : z4;
        } else {
            int f = (wn - 16) * 32 + lane;
            vb[w & 3] = (f < 125) ? __ldg(rI + f) : z4;
        }
        unsigned m0 = __ballot_sync(0xffffffffu, v.x != 0.f);
        unsigned m1 = __ballot_sync(0xffffffffu, v.y != 0.f);
        unsigned m2 = __ballot_sync(0xffffffffu, v.z != 0.f);
        unsigned m3 = __ballot_sync(0xffffffffu, v.w != 0.f);
        int b = w * 48 + lc;
        accE += __popc(m0 & sCE[b]);
        accE += __popc(m1 & sCE[b + 12]);
        accE += __popc(m2 & sCE[b + 24]);
        accE += __popc(m3 & sCE[b + 36]);
    }
    #pragma unroll
    for (int w = 0; w < 4; ++w) {
        float4 v = vb[w];
        unsigned m0 = __ballot_sync(0xffffffffu, v.x != 0.f);
        unsigned m1 = __ballot_sync(0xffffffffu, v.y != 0.f);
        unsigned m2 = __ballot_sync(0xffffffffu, v.z != 0.f);
        unsigned m3 = __ballot_sync(0xffffffffu, v.w != 0.f);
        int b = w * 48 + lc;
        accI += __popc(m0 & sCI[b]);
        accI += __popc(m1 & sCI[b + 12]);
        accI += __popc(m2 & sCI[b + 24]);
        accI += __popc(m3 & sCI[b + 36]);
    }
    if (lane < 12)
        g_INT2[(TOFF + row) * 12 + lane] = make_float2((float)accE, (float)accI);
}

// ---------------- K34 v2: fused conv + cascade, sliding window + f32x2 -------
// 148 blocks (one per SM) x 136 t, 384 threads = 12 warps (warp = subunit).
// Each lane owns 5 adjacent outputs m = 5*lane + j (m rel t0-12); one smem
// float2 load per tap serves all 5 outputs; 4 scalar FMA collapse into 2
// fma.rn.f32x2 on the (e,i)-packed operand. LDS bytes /5, FMA issue /2.
#define SS_OFF   0        // float [12*148] syn_s
#define SNS_OFF  1776     // float [12*148] syn_ns
#define XNO_OFF  3552     // float [12*148] cascade levels
#define SOUT_OFF 5328     // float [136*35]
#define BUFSZ    10088    // floats; sIN (348*12 float2 = 8352 floats) aliases 0

__global__ void __launch_bounds__(384) k34(const float* __restrict__ Cden,
                                           const float* __restrict__ Ths,
                                           const float* __restrict__ Thns,
                                           const float* __restrict__ Wssub,
                                           const float* __restrict__ Wnssub,
                                           float* __restrict__ out) {
    __shared__ __align__(16) float buf[BUFSZ];
    __shared__ float cwns[144], cds[144];
    __shared__ float ths[12], thns[12], ws[12], wns[12];
    int tid = threadIdx.x;
    int t0  = blockIdx.x * TILE;

    if (tid < 144) {
        float c = Cden[tid];
        cds [tid] = c;
        cwns[tid] = c * Wnssub[tid % 12];
    }
    if (tid >= 160 && tid < 172) {
        int q = tid - 160;
        ths [q] = Ths[q];
        thns[q] = Thns[q];
        ws  [q] = Wssub[q];
        wns [q] = Wnssub[q];
    }

    // ---- stage IN window: sIN[s][xx] = IN at t = t0 - 212 + xx, xx in [0,348) ----
    float2* sIN = (float2*)buf;                      // [s][xx], pitch 348
    {
        int base = (TOFF + t0 - 212) * 12;
        for (int i = tid; i < 4176; i += 384) {      // 348 * 12, coalesced
            int xx = i / 12, s = i % 12;
            sIN[s * 348 + xx] = g_INT2[base + i];
        }
    }
    __syncthreads();

    // ---- conv: warp s, lane owns outputs m = 5*lane + j (j<5), valid m<148 ----
    int warp = tid >> 5, lane = tid & 31;
    int s = warp;
    int mbase = 5 * lane;
    const unsigned long long* row =
        (const unsigned long long*)(sIN + s * 348);
    unsigned long long W0, W1, W2, W3, W4;
    unsigned long long aS0 = 0, aS1 = 0, aS2 = 0, aS3 = 0, aS4 = 0;
    unsigned long long aN0 = 0, aN1 = 0, aN2 = 0, aN3 = 0, aN4 = 0;
    W0 = row[min(mbase + 200, 347)];
    W1 = row[min(mbase + 201, 347)];
    W2 = row[min(mbase + 202, 347)];
    W3 = row[min(mbase + 203, 347)];
    W4 = row[min(mbase + 204, 347)];
    const float4* kp = g_KER4 + s * 200;
    #pragma unroll 5
    for (int k = 0; k < 200; ++k) {
        float4 kc = __ldg(kp + k);
        unsigned long long cs, cn;
        PACK2(cs, kc.x, kc.y);
        PACK2(cn, kc.z, kc.w);
        FMA2(aS0, W0, cs); FMA2(aN0, W0, cn);
        FMA2(aS1, W1, cs); FMA2(aN1, W1, cn);
        FMA2(aS2, W2, cs); FMA2(aN2, W2, cn);
        FMA2(aS3, W3, cs); FMA2(aN3, W3, cn);
        FMA2(aS4, W4, cs); FMA2(aN4, W4, cn);
        W4 = W3; W3 = W2; W2 = W1; W1 = W0;
        W0 = row[min(mbase + 199 - k, 347)];
    }
    __syncthreads();                                  // sIN dead; buf reusable

    // ---- write syn into sS / sNS (col m) ----
    {
        float lo, hi;
        #pragma unroll
        for (int j = 0; j < 5; ++j) {
            int m = mbase + j;
            if (m < 148) {
                unsigned long long vS, vN;
                switch (j) {
                    case 0: vS = aS0; vN = aN0; break;
                    case 1: vS = aS1; vN = aN1; break;
                    case 2: vS = aS2; vN = aN2; break;
                    case 3: vS = aS3; vN = aN3; break;
                    default: vS = aS4; vN = aN4; break;
                }
                UNPACK2(lo, hi, vS); buf[SS_OFF  + s * 148 + m] = lo + hi;
                UNPACK2(lo, hi, vN); buf[SNS_OFF + s * 148 + m] = lo + hi;
            }
        }
    }
    __syncthreads();

    // ---- cascade: 12 lower-triangular levels over cols m = 0..147 ----
    #pragma unroll
    for (int i = 0; i < 12; ++i) {
        if (tid < 148) {
            int t = t0 - 12 + tid;
            float v = 0.f;
            if (t >= 0) {
                float x = buf[SNS_OFF + i * 148 + tid] + thns[i];
                #pragma unroll
                for (int j = 0; j < i; ++j) {
                    float yp = (tid > 0) ? buf[XNO_OFF + j * 148 + tid - 1] : 0.f;
                    x = fmaf(cwns[i * 12 + j], yp, x);
                }
                v = sigmoidf_(x);
            }
            buf[XNO_OFF + i * 148 + tid] = v;
        }
        __syncthreads();
    }

    // ---- epilogue: per-t outputs ----
    if (tid < TILE) {
        int t = t0 + tid, h = tid + 12;
        if (t < T_DATA) {
            float ysp[12];
            if (t == 0) {
                #pragma unroll
                for (int j = 0; j < 12; ++j) ysp[j] = 0.f;
            } else {
                float x0 = buf[SS_OFF + 0 * 148 + tid + 11] + ths[0];
                ysp[0] = sigmoidf_(x0) * ws[0];
                #pragma unroll
                for (int j = 1; j < 12; ++j)
                    ysp[j] = buf[XNO_OFF + j * 148 + h - 1] * ws[j];
            }
            float* o = buf + SOUT_OFF + tid * 35;
            #pragma unroll
            for (int i = 0; i < 12; ++i) {
                float xs = buf[SS_OFF + i * 148 + tid + 12] + ths[i];
                #pragma unroll
                for (int j = 0; j < i; ++j) xs = fmaf(cds[i * 12 + j], ysp[j], xs);
                float sg  = sigmoidf_(xs);
                float xti = buf[XNO_OFF + i * 148 + h];
                o[i]      = (i == 0) ? sg * ws[0] : xti * ws[i];
                o[12 + i] = xti * wns[i];
                if (i >= 1) o[24 + i - 1] = sg;
            }
        }
    }
    __syncthreads();
    int nvalid = T_DATA - t0; if (nvalid > TILE) nvalid = TILE;
    float* ob = out + (size_t)t0 * 35;
    if (nvalid == TILE) {
        float4* o4 = (float4*)ob;                     // t0*35 % 4 == 0
        const float4* sb = (const float4*)(buf + SOUT_OFF);
        for (int i = tid; i < 1190; i += 384) o4[i] = sb[i];
    } else {
        int nf = nvalid * 35;
        for (int i = tid; i < nf; i += 384) ob[i] = buf[SOUT_OFF + i];
    }
}

// ---------------- launch ----------------
extern "C" void kernel_launch(void* const* d_in, const int* in_sizes, int n_in,
                              void* d_out, int out_size) {
    const float* S_e      = (const float*)d_in[0];
    const float* S_i      = (const float*)d_in[1];
    const float* C_syn_e  = (const float*)d_in[2];
    const float* C_syn_i  = (const float*)d_in[3];
    const float* C_den    = (const float*)d_in[4];
    const float* W_s_syn  = (const float*)d_in[5];
    const float* W_ns_syn = (const float*)d_in[6];
    const float* D_s      = (const float*)d_in[7];
    const float* D_ns     = (const float*)d_in[8];
    const float* Theta_s  = (const float*)d_in[9];
    const float* Theta_ns = (const float*)d_in[10];
    const float* W_s_sub  = (const float*)d_in[11];
    const float* W_ns_sub = (const float*)d_in[12];
    float* out = (float*)d_out;

    k0a<<<8, 960>>>((const float4*)C_syn_e, (const float4*)C_syn_i);
    k1f<<<2522, 256>>>((const float4*)S_e, (const float4*)S_i,
                       W_s_syn, W_ns_syn, D_s, D_ns);
    k34<<<148, 384>>>(C_den, Theta_s, Theta_ns, W_s_sub, W_ns_sub, out);
}